// round 5
// baseline (speedup 1.0000x reference)
#include <cuda_runtime.h>
#include <stdint.h>

// Problem constants (match reference)
#define HOP        160
#define FFT        1024
#define NUM_LABELS 72
#define BATCH      4
#define TLEN       240000
#define PAD        (FFT / 2)           // 512
#define LPAD       (TLEN + 2 * PAD)    // 241024
#define NOUT       ((LPAD - FFT) / HOP + 1)  // 1501

#define THREADS    256
#define W_PER_CTA  8
#define NCTA_X     ((NOUT + W_PER_CTA - 1) / W_PER_CTA)  // 188

__device__ __forceinline__ int reflect_idx(int j)
{
    int o = j - PAD;
    if (o < 0) o = -o;                          // left reflect (excl. edge)
    else if (o >= TLEN) o = 2 * (TLEN - 1) - o; // right reflect
    return o;
}

__global__ void __launch_bounds__(THREADS)
label_majority_sliding(const int* __restrict__ lbl, float* __restrict__ out)
{
    const int b   = blockIdx.y;
    const int w0  = blockIdx.x * W_PER_CTA;     // first window of this CTA
    const int tid = threadIdx.x;

    __shared__ int hist[NUM_LABELS];

    if (tid < NUM_LABELS) hist[tid] = 0;
    __syncthreads();

    const int* __restrict__ row = lbl + (size_t)b * TLEN;
    float* __restrict__ orow = out + (size_t)b * NOUT;

    // ---- initial window w0: full histogram (1024 adds, coalesced) ----
    const int start = w0 * HOP;
    #pragma unroll
    for (int k = 0; k < FFT / THREADS; k++) {
        int j = start + tid + k * THREADS;
        atomicAdd(&hist[row[reflect_idx(j)]], 1);
    }
    __syncthreads();

    // warp 0 scans 72 bins: pack count<<7 | (127-label) -> max = argmax w/
    // lowest-label tie-break (matches jnp.argmax).
    if (tid < 32) {
        int p = (hist[tid] << 7) | (127 - tid);
        int q = (hist[tid + 32] << 7) | (127 - (tid + 32));
        p = max(p, q);
        if (tid < NUM_LABELS - 64) {
            q = (hist[tid + 64] << 7) | (127 - (tid + 64));
            p = max(p, q);
        }
        #pragma unroll
        for (int off = 16; off > 0; off >>= 1)
            p = max(p, __shfl_xor_sync(0xFFFFFFFFu, p, off));
        if (tid == 0) orow[w0] = (float)(127 - (p & 127));
    }

    // ---- sliding: each next window removes HOP old, adds HOP new ----
    #pragma unroll
    for (int i = 1; i < W_PER_CTA; i++) {
        const int w = w0 + i;
        if (w >= NOUT) break;
        __syncthreads();   // scan of previous window must finish before updates
        if (tid < HOP) {
            int jold = (w - 1) * HOP + tid;          // leaving the window
            int jnew = (w - 1) * HOP + FFT + tid;    // entering the window
            atomicSub(&hist[row[reflect_idx(jold)]], 1);
            atomicAdd(&hist[row[reflect_idx(jnew)]], 1);
        }
        __syncthreads();   // updates done -> scan

        if (tid < 32) {
            int p = (hist[tid] << 7) | (127 - tid);
            int q = (hist[tid + 32] << 7) | (127 - (tid + 32));
            p = max(p, q);
            if (tid < NUM_LABELS - 64) {
                q = (hist[tid + 64] << 7) | (127 - (tid + 64));
                p = max(p, q);
            }
            #pragma unroll
            for (int off = 16; off > 0; off >>= 1)
                p = max(p, __shfl_xor_sync(0xFFFFFFFFu, p, off));
            if (tid == 0) orow[w] = (float)(127 - (p & 127));
        }
    }
}

extern "C" void kernel_launch(void* const* d_in, const int* in_sizes, int n_in,
                              void* d_out, int out_size)
{
    const int* lbl = (const int*)d_in[0];   // [B, T] int32
    // d_in[1]: all-ones conv weight — irrelevant (window sum == histogram).
    float* out = (float*)d_out;             // [B, NOUT] compared as float32

    dim3 grid(NCTA_X, BATCH);
    label_majority_sliding<<<grid, THREADS>>>(lbl, out);
}

// round 6
// speedup vs baseline: 1.2330x; 1.2330x over previous
#include <cuda_runtime.h>
#include <stdint.h>

// Problem constants (match reference)
#define HOP        160
#define FFT        1024
#define NUM_LABELS 72
#define BATCH      4
#define TLEN       240000
#define PAD        (FFT / 2)           // 512
#define LPAD       (TLEN + 2 * PAD)    // 241024
#define NOUT       ((LPAD - FFT) / HOP + 1)  // 1501

#define W_RUN          4                          // windows per warp (sliding)
#define WARPS_PER_CTA  2
#define BLOCK          (WARPS_PER_CTA * 32)
#define RUNS_PER_B     ((NOUT + W_RUN - 1) / W_RUN)              // 376
#define CTAS_X         ((RUNS_PER_B + WARPS_PER_CTA - 1) / WARPS_PER_CTA)  // 188

__device__ __forceinline__ int reflect_idx(int j)
{
    int o = j - PAD;
    if (o < 0) o = -o;                          // left reflect (excl. edge)
    else if (o >= TLEN) o = 2 * (TLEN - 1) - o; // right reflect
    return o;
}

// Warp-wide argmax over the 72-bin histogram with lowest-label tie-break
// (matches jnp.argmax): pack count<<7 | (127-label), take max.
__device__ __forceinline__ void scan_and_write(const int* __restrict__ h,
                                               float* __restrict__ orow,
                                               int w, int lane)
{
    int p = (h[lane] << 7) | (127 - lane);
    int q = (h[lane + 32] << 7) | (127 - (lane + 32));
    p = max(p, q);
    if (lane < NUM_LABELS - 64) {
        q = (h[lane + 64] << 7) | (127 - (lane + 64));
        p = max(p, q);
    }
    #pragma unroll
    for (int off = 16; off > 0; off >>= 1)
        p = max(p, __shfl_xor_sync(0xFFFFFFFFu, p, off));
    if (lane == 0) orow[w] = (float)(127 - (p & 127));
}

__global__ void __launch_bounds__(BLOCK)
label_majority_warpslide(const int* __restrict__ lbl, float* __restrict__ out)
{
    __shared__ int hist[WARPS_PER_CTA][NUM_LABELS];

    const int lane = threadIdx.x & 31;
    const int wid  = threadIdx.x >> 5;
    const int b    = blockIdx.y;
    const int run  = blockIdx.x * WARPS_PER_CTA + wid;   // 0..RUNS_PER_B-1
    if (run >= RUNS_PER_B) return;

    const int w0 = run * W_RUN;

    const int* __restrict__ row  = lbl + (size_t)b * TLEN;
    float* __restrict__     orow = out + (size_t)b * NOUT;
    int* __restrict__       h    = hist[wid];

    // zero private histogram
    h[lane] = 0;
    h[lane + 32] = 0;
    if (lane < NUM_LABELS - 64) h[lane + 64] = 0;
    __syncwarp();

    // ---- initial window w0: full 1024-element histogram ----
    const int start = w0 * HOP;
    #pragma unroll
    for (int k = 0; k < FFT / 32; k++) {
        int j = start + lane + k * 32;
        atomicAdd(&h[row[reflect_idx(j)]], 1);
    }
    __syncwarp();
    scan_and_write(h, orow, w0, lane);

    // ---- slide: each next window removes HOP old, adds HOP new ----
    #pragma unroll
    for (int i = 1; i < W_RUN; i++) {
        const int w = w0 + i;
        if (w >= NOUT) break;
        __syncwarp();   // scan reads must complete before histogram updates
        const int base = (w - 1) * HOP;
        #pragma unroll
        for (int k = 0; k < HOP / 32; k++) {
            int jo = base + lane + k * 32;        // leaving
            int jn = base + FFT + lane + k * 32;  // entering
            atomicSub(&h[row[reflect_idx(jo)]], 1);
            atomicAdd(&h[row[reflect_idx(jn)]], 1);
        }
        __syncwarp();   // updates visible before scan
        scan_and_write(h, orow, w, lane);
    }
}

extern "C" void kernel_launch(void* const* d_in, const int* in_sizes, int n_in,
                              void* d_out, int out_size)
{
    const int* lbl = (const int*)d_in[0];   // [B, T] int32
    // d_in[1]: all-ones conv weight — irrelevant (window sum == histogram).
    float* out = (float*)d_out;             // [B, NOUT], compared as float32

    dim3 grid(CTAS_X, BATCH);
    label_majority_warpslide<<<grid, BLOCK>>>(lbl, out);
}

// round 7
// speedup vs baseline: 1.6618x; 1.3478x over previous
#include <cuda_runtime.h>
#include <stdint.h>

// Problem constants (match reference)
#define HOP        160
#define FFT        1024
#define NUM_LABELS 72
#define BATCH      4
#define TLEN       240000
#define PAD        (FFT / 2)           // 512
#define LPAD       (TLEN + 2 * PAD)    // 241024
#define NOUT       ((LPAD - FFT) / HOP + 1)  // 1501

#define W_RUN          4
#define WARPS_PER_CTA  4
#define BLOCK          (WARPS_PER_CTA * 32)
#define RUNS_PER_B     ((NOUT + W_RUN - 1) / W_RUN)                        // 376
#define CTAS_X         ((RUNS_PER_B + WARPS_PER_CTA - 1) / WARPS_PER_CTA)  // 94

// Interior run range: all accessed unpadded indices within [0, TLEN)
// w0 >= 4 and w0 <= 1493  (w0 = 4*run -> run in [1, 373])
#define RUN_INT_LO 1
#define RUN_INT_HI 373

__device__ __forceinline__ int reflect_idx(int j)
{
    int o = j - PAD;
    if (o < 0) o = -o;
    else if (o >= TLEN) o = 2 * (TLEN - 1) - o;
    return o;
}

// Warp-wide argmax over 72 bins, lowest-label tie-break (matches jnp.argmax):
// pack count<<7 | (127-label), take max.
__device__ __forceinline__ void scan_and_write(const int* __restrict__ h,
                                               float* __restrict__ orow,
                                               int w, int lane)
{
    int p = (h[lane] << 7) | (127 - lane);
    int q = (h[lane + 32] << 7) | (127 - (lane + 32));
    p = max(p, q);
    if (lane < NUM_LABELS - 64) {
        q = (h[lane + 64] << 7) | (127 - (lane + 64));
        p = max(p, q);
    }
    #pragma unroll
    for (int off = 16; off > 0; off >>= 1)
        p = max(p, __shfl_xor_sync(0xFFFFFFFFu, p, off));
    if (lane == 0) orow[w] = (float)(127 - (p & 127));
}

__global__ void __launch_bounds__(BLOCK)
label_majority_warpslide2(const int* __restrict__ lbl, float* __restrict__ out)
{
    __shared__ int hist[WARPS_PER_CTA][NUM_LABELS];

    const int lane = threadIdx.x & 31;
    const int wid  = threadIdx.x >> 5;
    const int b    = blockIdx.y;
    const int run  = blockIdx.x * WARPS_PER_CTA + wid;
    if (run >= RUNS_PER_B) return;

    const int w0 = run * W_RUN;

    const int* __restrict__ row  = lbl + (size_t)b * TLEN;
    float* __restrict__     orow = out + (size_t)b * NOUT;
    int* __restrict__       h    = hist[wid];

    // zero private histogram
    h[lane] = 0;
    h[lane + 32] = 0;
    if (lane < NUM_LABELS - 64) h[lane + 64] = 0;
    __syncwarp();

    if (run >= RUN_INT_LO && run <= RUN_INT_HI) {
        // ================= interior fast path (branch-free, vectorized) ====
        // unpadded start offset; multiple of 16 elements -> int4 aligned
        const int* __restrict__ base = row + (w0 * HOP - PAD);

        // ---- build window w0: 8 x int4 per lane (MLP), then 32 atomics ----
        int4 v[8];
        #pragma unroll
        for (int k = 0; k < 8; k++)
            v[k] = *(const int4*)(base + k * 128 + lane * 4);
        #pragma unroll
        for (int k = 0; k < 8; k++) {
            atomicAdd(&h[v[k].x], 1);
            atomicAdd(&h[v[k].y], 1);
            atomicAdd(&h[v[k].z], 1);
            atomicAdd(&h[v[k].w], 1);
        }
        __syncwarp();

        // ---- slide: prefetch labels, scan previous window, then update ----
        #pragma unroll
        for (int i = 1; i < W_RUN; i++) {
            const int* __restrict__ ob = base + (i - 1) * HOP;  // leaving
            const int* __restrict__ nb = ob + FFT;              // entering
            // prefetch 160 old + 160 new: int4 covers 128, scalar covers 32
            int4 o4 = *(const int4*)(ob + lane * 4);
            int  os = ob[128 + lane];
            int4 n4 = *(const int4*)(nb + lane * 4);
            int  ns = nb[128 + lane];

            scan_and_write(h, orow, w0 + i - 1, lane);
            __syncwarp();   // scan reads done before updates

            atomicSub(&h[o4.x], 1); atomicSub(&h[o4.y], 1);
            atomicSub(&h[o4.z], 1); atomicSub(&h[o4.w], 1);
            atomicSub(&h[os], 1);
            atomicAdd(&h[n4.x], 1); atomicAdd(&h[n4.y], 1);
            atomicAdd(&h[n4.z], 1); atomicAdd(&h[n4.w], 1);
            atomicAdd(&h[ns], 1);
            __syncwarp();   // updates visible before next scan
        }
        scan_and_write(h, orow, w0 + W_RUN - 1, lane);
    } else {
        // ================= edge path (reflect handling, scalar) ============
        const int start = w0 * HOP;
        #pragma unroll
        for (int k = 0; k < FFT / 32; k++) {
            int j = start + lane + k * 32;
            atomicAdd(&h[row[reflect_idx(j)]], 1);
        }
        __syncwarp();
        scan_and_write(h, orow, w0, lane);

        #pragma unroll
        for (int i = 1; i < W_RUN; i++) {
            const int w = w0 + i;
            if (w >= NOUT) break;
            __syncwarp();
            const int bidx = (w - 1) * HOP;
            #pragma unroll
            for (int k = 0; k < HOP / 32; k++) {
                int jo = bidx + lane + k * 32;
                int jn = bidx + FFT + lane + k * 32;
                atomicSub(&h[row[reflect_idx(jo)]], 1);
                atomicAdd(&h[row[reflect_idx(jn)]], 1);
            }
            __syncwarp();
            scan_and_write(h, orow, w, lane);
        }
    }
}

extern "C" void kernel_launch(void* const* d_in, const int* in_sizes, int n_in,
                              void* d_out, int out_size)
{
    const int* lbl = (const int*)d_in[0];   // [B, T] int32
    // d_in[1]: all-ones conv weight — irrelevant (window sum == histogram).
    float* out = (float*)d_out;             // [B, NOUT], compared as float32

    dim3 grid(CTAS_X, BATCH);
    label_majority_warpslide2<<<grid, BLOCK>>>(lbl, out);
}